// round 5
// baseline (speedup 1.0000x reference)
#include <cuda_runtime.h>
#include <math.h>

#define BATCH 4
#define LQ 2048
#define LK 2048
#define DMODEL 512
#define NH 2
#define DK 64
#define DV 64
#define QKV_N 128

#define BQ 128
#define BK 128
#define NT 512

#define Q_STR 132
#define K_STR 132
#define OFF_Q 0
#define OFF_K (OFF_Q + DK * Q_STR)
#define OFF_V (OFF_K + DK * K_STR)
#define OFF_S (OFF_V + BK * DV)
#define OFF_RL (OFF_S + BK * BQ)
#define OFF_LSE (OFF_RL + BQ)
#define OFF_MSK (OFF_LSE + BQ)
#define SMEM_FLOATS (OFF_MSK + BK)
#define SMEM_BYTES (SMEM_FLOATS * 4)

typedef unsigned long long ull;

__device__ __forceinline__ ull pk2(float x, float y)
{ ull r; asm("mov.b64 %0,{%1,%2};" : "=l"(r) : "f"(x), "f"(y)); return r; }
__device__ __forceinline__ ull bc2(float x) { return pk2(x, x); }
__device__ __forceinline__ void fma2(ull& d, ull a, ull b)
{ asm("fma.rn.f32x2 %0,%1,%2,%0;" : "+l"(d) : "l"(a), "l"(b)); }
__device__ __forceinline__ float2 up2(ull v)
{ float2 r; asm("mov.b64 {%0,%1},%2;" : "=f"(r.x), "=f"(r.y) : "l"(v)); return r; }

__device__ __forceinline__ int s_off(int kc, int g)
{ return OFF_S + kc * BQ + (((g + kc + (kc >> 3)) & 31) << 2); }

// 10*tanh(x) = 10 - 20/(exp(2x)+1); exact at +/-inf, no clamp needed
__device__ __forceinline__ float tanh10(float x)
{
    float e = __expf(2.f * x);
    float r;
    asm("rcp.approx.f32 %0,%1;" : "=f"(r) : "f"(e + 1.f));
    return fmaf(-20.f, r, 10.f);
}

__device__ float g_q[BATCH * LQ * QKV_N];
__device__ float g_k[BATCH * LK * QKV_N];
__device__ float g_v[BATCH * LK * QKV_N];
__device__ float g_otmp[BATCH * LQ * QKV_N];
__device__ float g_vsum[BATCH * QKV_N];
__device__ int g_mask_mode;  // 0=u8, 1=i32, 2=f32

__global__ void detect_mask_kernel(const unsigned int* __restrict__ w)
{
    __shared__ int s_f32, s_all01;
    if (threadIdx.x == 0) { s_f32 = 0; s_all01 = 1; }
    __syncthreads();
    int f = 0, bad = 0;
    for (int i = threadIdx.x; i < 2048; i += blockDim.x) {
        unsigned v = w[i];
        if (v == 0x3F800000u) f = 1;
        if (v > 1u) bad = 1;
    }
    if (f) atomicOr(&s_f32, 1);
    if (bad) atomicExch(&s_all01, 0);
    __syncthreads();
    if (threadIdx.x == 0) g_mask_mode = s_f32 ? 2 : (s_all01 ? 1 : 0);
}

// ---- fused QKV projection
__global__ __launch_bounds__(256) void gemm_qkv_kernel(
    const float* __restrict__ X0, const float* __restrict__ X1, const float* __restrict__ X2,
    const float* __restrict__ W0, const float* __restrict__ W1, const float* __restrict__ W2,
    const float* __restrict__ B0, const float* __restrict__ B1, const float* __restrict__ B2,
    float* __restrict__ Y0, float* __restrict__ Y1, float* __restrict__ Y2)
{
    __shared__ float xs[32 * 68];
    __shared__ float ws[32 * 132];
    int sel = blockIdx.y;
    const float* X = sel == 0 ? X0 : (sel == 1 ? X1 : X2);
    const float* W = sel == 0 ? W0 : (sel == 1 ? W1 : W2);
    const float* bias = sel == 0 ? B0 : (sel == 1 ? B1 : B2);
    float* Y = sel == 0 ? Y0 : (sel == 1 ? Y1 : Y2);

    int tid = threadIdx.x;
    int tx = tid & 15, ty = tid >> 4;
    int bm = blockIdx.x * 64;
    int row0 = ty * 4, col0 = tx * 8;

    ull acc2[4][4];
#pragma unroll
    for (int i = 0; i < 4; i++)
#pragma unroll
        for (int j = 0; j < 4; j++) acc2[i][j] = 0ull;

    for (int k0 = 0; k0 < DMODEL; k0 += 32) {
#pragma unroll
        for (int i = 0; i < 2; i++) {
            int linear = tid + i * 256;
            int m = linear >> 3;
            int g = (linear & 7) * 4;
            float4 v = *(const float4*)&X[(size_t)(bm + m) * DMODEL + k0 + g];
            xs[(g + 0) * 68 + m] = v.x;
            xs[(g + 1) * 68 + m] = v.y;
            xs[(g + 2) * 68 + m] = v.z;
            xs[(g + 3) * 68 + m] = v.w;
        }
#pragma unroll
        for (int i = 0; i < 4; i++) {
            int linear = tid + i * 256;
            int k = linear >> 5;
            int g = (linear & 31) * 4;
            *(float4*)&ws[k * 132 + g] = *(const float4*)&W[(size_t)(k0 + k) * QKV_N + g];
        }
        __syncthreads();
#pragma unroll
        for (int k = 0; k < 32; k++) {
            float4 xa = *(const float4*)&xs[k * 68 + row0];
            float4 wa = *(const float4*)&ws[k * 132 + col0];
            float4 wb = *(const float4*)&ws[k * 132 + col0 + 4];
            ull wp[4] = {pk2(wa.x, wa.y), pk2(wa.z, wa.w),
                         pk2(wb.x, wb.y), pk2(wb.z, wb.w)};
            ull xb[4] = {bc2(xa.x), bc2(xa.y), bc2(xa.z), bc2(xa.w)};
#pragma unroll
            for (int i = 0; i < 4; i++)
#pragma unroll
                for (int j = 0; j < 4; j++)
                    fma2(acc2[i][j], xb[i], wp[j]);
        }
        __syncthreads();
    }
    float bb[8];
#pragma unroll
    for (int j = 0; j < 8; j++) bb[j] = bias[col0 + j];
#pragma unroll
    for (int i = 0; i < 4; i++) {
        float2 a0 = up2(acc2[i][0]), a1 = up2(acc2[i][1]);
        float2 a2 = up2(acc2[i][2]), a3 = up2(acc2[i][3]);
        float* yp = &Y[(size_t)(bm + row0 + i) * QKV_N + col0];
        *(float4*)yp = make_float4(a0.x + bb[0], a0.y + bb[1], a1.x + bb[2], a1.y + bb[3]);
        *(float4*)(yp + 4) = make_float4(a2.x + bb[4], a2.y + bb[5], a3.x + bb[6], a3.y + bb[7]);
    }
}

// ---- out-proj GEMM
__global__ __launch_bounds__(256) void gemm_bias_kernel(
    const float* __restrict__ X, const float* __restrict__ W,
    const float* __restrict__ bias, float* __restrict__ Y,
    int M, int K, int N)
{
    __shared__ float xs[32 * 68];
    __shared__ float ws[32 * 132];
    int tid = threadIdx.x;
    int tx = tid & 15, ty = tid >> 4;
    int bm = blockIdx.x * 64, bn = blockIdx.y * 128;
    int row0 = ty * 4, col0 = tx * 8;

    ull acc2[4][4];
#pragma unroll
    for (int i = 0; i < 4; i++)
#pragma unroll
        for (int j = 0; j < 4; j++) acc2[i][j] = 0ull;

    for (int k0 = 0; k0 < K; k0 += 32) {
#pragma unroll
        for (int i = 0; i < 2; i++) {
            int linear = tid + i * 256;
            int m = linear >> 3;
            int g = (linear & 7) * 4;
            float4 v = *(const float4*)&X[(size_t)(bm + m) * K + k0 + g];
            xs[(g + 0) * 68 + m] = v.x;
            xs[(g + 1) * 68 + m] = v.y;
            xs[(g + 2) * 68 + m] = v.z;
            xs[(g + 3) * 68 + m] = v.w;
        }
#pragma unroll
        for (int i = 0; i < 4; i++) {
            int linear = tid + i * 256;
            int k = linear >> 5;
            int g = (linear & 31) * 4;
            *(float4*)&ws[k * 132 + g] = *(const float4*)&W[(size_t)(k0 + k) * N + bn + g];
        }
        __syncthreads();
#pragma unroll
        for (int k = 0; k < 32; k++) {
            float4 xa = *(const float4*)&xs[k * 68 + row0];
            float4 wa = *(const float4*)&ws[k * 132 + col0];
            float4 wb = *(const float4*)&ws[k * 132 + col0 + 4];
            ull wp[4] = {pk2(wa.x, wa.y), pk2(wa.z, wa.w),
                         pk2(wb.x, wb.y), pk2(wb.z, wb.w)};
            ull xb[4] = {bc2(xa.x), bc2(xa.y), bc2(xa.z), bc2(xa.w)};
#pragma unroll
            for (int i = 0; i < 4; i++)
#pragma unroll
                for (int j = 0; j < 4; j++)
                    fma2(acc2[i][j], xb[i], wp[j]);
        }
        __syncthreads();
    }
    float bb[8];
#pragma unroll
    for (int j = 0; j < 8; j++) bb[j] = bias[bn + col0 + j];
#pragma unroll
    for (int i = 0; i < 4; i++) {
        float2 a0 = up2(acc2[i][0]), a1 = up2(acc2[i][1]);
        float2 a2 = up2(acc2[i][2]), a3 = up2(acc2[i][3]);
        float* yp = &Y[(size_t)(bm + row0 + i) * N + bn + col0];
        *(float4*)yp = make_float4(a0.x + bb[0], a0.y + bb[1], a1.x + bb[2], a1.y + bb[3]);
        *(float4*)(yp + 4) = make_float4(a2.x + bb[4], a2.y + bb[5], a3.x + bb[6], a3.y + bb[7]);
    }
}

__global__ void vsum_zero_kernel() { g_vsum[threadIdx.x] = 0.f; }

__global__ __launch_bounds__(256) void vsum_kernel()
{
    __shared__ float red[8][128];
    int b = blockIdx.x, part = blockIdx.y;
    int c4 = (threadIdx.x & 31) * 4;
    int r0 = threadIdx.x >> 5;
    const float* base = g_v + ((size_t)b * LK + part * 128) * QKV_N;
    float4 s = make_float4(0.f, 0.f, 0.f, 0.f);
#pragma unroll 4
    for (int r = r0; r < 128; r += 8) {
        float4 v = *(const float4*)&base[(size_t)r * QKV_N + c4];
        s.x += v.x; s.y += v.y; s.z += v.z; s.w += v.w;
    }
    *(float4*)&red[r0][c4] = s;
    __syncthreads();
    if (threadIdx.x < 128) {
        float t = 0.f;
#pragma unroll
        for (int i = 0; i < 8; i++) t += red[i][threadIdx.x];
        atomicAdd(&g_vsum[b * QKV_N + threadIdx.x], t);
    }
}

// one block = 128 queries for one (b,h); 512 threads; frag 4x8 QK, 4x4 SV
__global__ __launch_bounds__(NT) void mab_main_kernel(
    const void* __restrict__ maskp, float* __restrict__ attn)
{
    extern __shared__ float sm[];
    int tid = threadIdx.x;
    int tx = tid & 15, ty = tid >> 4;      // ty 0..31
    int m0 = ty * 4;                        // 4 query rows per thread
    int nk = tx * 8;                        // 8 keys per thread (QK phase)
    int nv = tx * 4;                        // 4 dv per thread (SV phase)
    int q0 = blockIdx.x * BQ;
    int h = blockIdx.y, b = blockIdx.z;
    int mode = g_mask_mode;

    const float* qbase = g_q + ((size_t)b * LQ + q0) * QKV_N + h * DK;
#pragma unroll
    for (int i = 0; i < 4; i++) {
        int linear = tid + i * NT;
        int m = linear >> 4;
        int d = (linear & 15) * 4;
        float4 v = *(const float4*)&qbase[(size_t)m * QKV_N + d];
        sm[OFF_Q + (d + 0) * Q_STR + m] = v.x * 0.125f;
        sm[OFF_Q + (d + 1) * Q_STR + m] = v.y * 0.125f;
        sm[OFF_Q + (d + 2) * Q_STR + m] = v.z * 0.125f;
        sm[OFF_Q + (d + 3) * Q_STR + m] = v.w * 0.125f;
    }
    if (tid < BQ) sm[OFF_RL + tid] = 0.f;

    ull sv2[2][4];
#pragma unroll
    for (int i = 0; i < 2; i++)
#pragma unroll
        for (int j = 0; j < 4; j++) sv2[i][j] = 0ull;

    const float* kbase = g_k + (size_t)b * LK * QKV_N + h * DK;
    const float* vbase = g_v + (size_t)b * LK * QKV_N + h * DK;
    float* arow = attn + ((size_t)((b * NH + h) * LQ + q0)) * LK;

    __syncthreads();

    for (int c = 0; c < LK / BK; c++) {
        int k0 = c * BK;
#pragma unroll
        for (int i = 0; i < 4; i++) {
            int linear = tid + i * NT;
            int kr = linear >> 4;
            int d = (linear & 15) * 4;
            float4 v = *(const float4*)&kbase[(size_t)(k0 + kr) * QKV_N + d];
            sm[OFF_K + (d + 0) * K_STR + kr] = v.x;
            sm[OFF_K + (d + 1) * K_STR + kr] = v.y;
            sm[OFF_K + (d + 2) * K_STR + kr] = v.z;
            sm[OFF_K + (d + 3) * K_STR + kr] = v.w;
        }
#pragma unroll
        for (int i = 0; i < 4; i++) {
            int linear = tid + i * NT;
            int kr = linear >> 4;
            int d = (linear & 15) * 4;
            *(float4*)&sm[OFF_V + kr * DV + d] =
                *(const float4*)&vbase[(size_t)(k0 + kr) * QKV_N + d];
        }
        if (tid < BK) {
            size_t gi = (size_t)b * LK + k0 + tid;
            int mm;
            if (mode == 1)      mm = ((const int*)maskp)[gi] != 0;
            else if (mode == 0) mm = ((const unsigned char*)maskp)[gi] != 0;
            else                mm = ((const float*)maskp)[gi] != 0.f;
            sm[OFF_MSK + tid] = mm ? 1.f : 0.f;
        }
        __syncthreads();

        // phase 1: S = q @ k^T, 4 queries x 8 keys per thread
        ull acc2[2][8];
#pragma unroll
        for (int p = 0; p < 2; p++)
#pragma unroll
            for (int j = 0; j < 8; j++) acc2[p][j] = 0ull;

#pragma unroll 4
        for (int d = 0; d < DK; d++) {
            float4 qa = *(const float4*)&sm[OFF_Q + d * Q_STR + m0];
            float4 ka = *(const float4*)&sm[OFF_K + d * K_STR + nk];
            float4 kb4 = *(const float4*)&sm[OFF_K + d * K_STR + nk + 4];
            ull qp[2] = {pk2(qa.x, qa.y), pk2(qa.z, qa.w)};
            ull kb[8] = {bc2(ka.x), bc2(ka.y), bc2(ka.z), bc2(ka.w),
                         bc2(kb4.x), bc2(kb4.y), bc2(kb4.z), bc2(kb4.w)};
#pragma unroll
            for (int p = 0; p < 2; p++)
#pragma unroll
                for (int j = 0; j < 8; j++)
                    fma2(acc2[p][j], qp[p], kb[j]);
        }

        float acc[4][8];
#pragma unroll
        for (int p = 0; p < 2; p++)
#pragma unroll
            for (int j = 0; j < 8; j++) {
                float2 v = up2(acc2[p][j]);
                acc[2 * p][j] = v.x;
                acc[2 * p + 1][j] = v.y;
            }

        float mk[8];
#pragma unroll
        for (int j = 0; j < 8; j++) mk[j] = sm[OFF_MSK + nk + j];

        float er[4];
#pragma unroll
        for (int i = 0; i < 4; i++) {
            float rs = 0.f;
#pragma unroll
            for (int j = 0; j < 8; j++) {
                float s = tanh10(acc[i][j]);
                if (mk[j] != 0.f) s = -10.f;
                acc[i][j] = s;
                rs += __expf(s);
            }
            er[i] = rs;
            float* ap = &arow[(size_t)(m0 + i) * LK + k0 + nk];
            *(float4*)ap = make_float4(acc[i][0], acc[i][1], acc[i][2], acc[i][3]);
            *(float4*)(ap + 4) = make_float4(acc[i][4], acc[i][5], acc[i][6], acc[i][7]);
        }
        // butterfly-reduce exp sums over the 16 tx lanes (stays in half-warp)
#pragma unroll
        for (int d = 1; d < 16; d <<= 1) {
#pragma unroll
            for (int i = 0; i < 4; i++)
                er[i] += __shfl_xor_sync(0xffffffffu, er[i], d);
        }
        if (tx == 0) {
#pragma unroll
            for (int i = 0; i < 4; i++)
                sm[OFF_RL + m0 + i] += er[i];
        }
        // S tile to smem, queries packed per float4
#pragma unroll
        for (int j = 0; j < 8; j++) {
            int kc = nk + j;
            *(float4*)&sm[s_off(kc, ty)] =
                make_float4(acc[0][j], acc[1][j], acc[2][j], acc[3][j]);
        }
        __syncthreads();

        // phase 2: SV += S_chunk @ v_chunk (4 queries x 4 dv per thread)
#pragma unroll 8
        for (int kc = 0; kc < BK; kc++) {
            float4 sa = *(const float4*)&sm[s_off(kc, ty)];
            float4 vv = *(const float4*)&sm[OFF_V + kc * DV + nv];
            ull sp[2] = {pk2(sa.x, sa.y), pk2(sa.z, sa.w)};
            ull vb[4] = {bc2(vv.x), bc2(vv.y), bc2(vv.z), bc2(vv.w)};
#pragma unroll
            for (int p = 0; p < 2; p++)
#pragma unroll
                for (int j = 0; j < 4; j++)
                    fma2(sv2[p][j], sp[p], vb[j]);
        }
        __syncthreads();
    }

    if (tid < BQ) sm[OFF_LSE + tid] = logf(sm[OFF_RL + tid]);
    __syncthreads();

    {   // otmp = SV - lse * vsum
        float4 vs = *(const float4*)&g_vsum[(b * NH + h) * DV + nv];
#pragma unroll
        for (int p = 0; p < 2; p++) {
            float2 c0 = up2(sv2[p][0]), c1 = up2(sv2[p][1]);
            float2 c2 = up2(sv2[p][2]), c3 = up2(sv2[p][3]);
            float l0 = sm[OFF_LSE + m0 + 2 * p];
            float l1 = sm[OFF_LSE + m0 + 2 * p + 1];
            size_t r0 = ((size_t)b * LQ + q0 + m0 + 2 * p) * QKV_N + h * DK + nv;
            *(float4*)&g_otmp[r0] =
                make_float4(c0.x - l0 * vs.x, c1.x - l0 * vs.y,
                            c2.x - l0 * vs.z, c3.x - l0 * vs.w);
            *(float4*)&g_otmp[r0 + QKV_N] =
                make_float4(c0.y - l1 * vs.x, c1.y - l1 * vs.y,
                            c2.y - l1 * vs.z, c3.y - l1 * vs.w);
        }
    }

    float lr[4];
#pragma unroll
    for (int i = 0; i < 4; i++) lr[i] = sm[OFF_LSE + m0 + i];
    for (int c = 0; c < LK / BK; c++) {
#pragma unroll
        for (int i = 0; i < 4; i++) {
            float* ap = &arow[(size_t)(m0 + i) * LK + c * BK + nk];
            float4 a = *(float4*)ap;
            a.x -= lr[i]; a.y -= lr[i]; a.z -= lr[i]; a.w -= lr[i];
            *(float4*)ap = a;
            float4 b4 = *(float4*)(ap + 4);
            b4.x -= lr[i]; b4.y -= lr[i]; b4.z -= lr[i]; b4.w -= lr[i];
            *(float4*)(ap + 4) = b4;
        }
    }
}

extern "C" void kernel_launch(void* const* d_in, const int* in_sizes, int n_in,
                              void* d_out, int out_size)
{
    const float* Q  = (const float*)d_in[0];
    const float* K  = (const float*)d_in[1];
    const float* V  = (const float*)d_in[2];
    const void*  Mk = d_in[3];
    const float* Wq = (const float*)d_in[4];
    const float* bq = (const float*)d_in[5];
    const float* Wk = (const float*)d_in[6];
    const float* bk = (const float*)d_in[7];
    const float* Wv = (const float*)d_in[8];
    const float* bv = (const float*)d_in[9];
    const float* Wo = (const float*)d_in[10];
    const float* bo = (const float*)d_in[11];

    float* out  = (float*)d_out;
    float* attn = out + (size_t)BATCH * LQ * DMODEL;

    float *gq, *gk, *gv, *gotmp;
    cudaGetSymbolAddress((void**)&gq, g_q);
    cudaGetSymbolAddress((void**)&gk, g_k);
    cudaGetSymbolAddress((void**)&gv, g_v);
    cudaGetSymbolAddress((void**)&gotmp, g_otmp);

    static int smem_set = 0;
    if (!smem_set) {
        cudaFuncSetAttribute(mab_main_kernel,
                             cudaFuncAttributeMaxDynamicSharedMemorySize, SMEM_BYTES);
        smem_set = 1;
    }

    detect_mask_kernel<<<1, 256>>>((const unsigned int*)Mk);

    const int M = BATCH * LQ;  // 8192
    gemm_qkv_kernel<<<dim3(M / 64, 3), 256>>>(Q, K, V, Wq, Wk, Wv,
                                              bq, bk, bv, gq, gk, gv);

    vsum_zero_kernel<<<1, BATCH * QKV_N>>>();
    vsum_kernel<<<dim3(BATCH, 16), 256>>>();

    mab_main_kernel<<<dim3(LQ / BQ, NH, BATCH), NT, SMEM_BYTES>>>(Mk, attn);

    gemm_bias_kernel<<<dim3(M / 64, DMODEL / 128), 256>>>(gotmp, Wo, bo, out,
                                                          M, QKV_N, DMODEL);
}

// round 6
// speedup vs baseline: 1.1560x; 1.1560x over previous
#include <cuda_runtime.h>
#include <math.h>

#define BATCH 4
#define LQ 2048
#define LK 2048
#define DMODEL 512
#define NH 2
#define DK 64
#define DV 64
#define QKV_N 128

#define BQ 128
#define BK 128

#define Q_STR 132
#define K_STR 132
#define OFF_Q 0
#define OFF_K (OFF_Q + DK * Q_STR)
#define OFF_V (OFF_K + DK * K_STR)
#define OFF_S (OFF_V + BK * DV)
#define OFF_RL (OFF_S + BK * BQ)
#define OFF_LSE (OFF_RL + BQ)
#define OFF_MSK (OFF_LSE + BQ)
#define SMEM_FLOATS (OFF_MSK + BK)
#define SMEM_BYTES (SMEM_FLOATS * 4)

typedef unsigned long long ull;

__device__ __forceinline__ ull pk2(float x, float y)
{ ull r; asm("mov.b64 %0,{%1,%2};" : "=l"(r) : "f"(x), "f"(y)); return r; }
__device__ __forceinline__ ull bc2(float x) { return pk2(x, x); }
__device__ __forceinline__ void fma2(ull& d, ull a, ull b)
{ asm("fma.rn.f32x2 %0,%1,%2,%0;" : "+l"(d) : "l"(a), "l"(b)); }
__device__ __forceinline__ float2 up2(ull v)
{ float2 r; asm("mov.b64 {%0,%1},%2;" : "=f"(r.x), "=f"(r.y) : "l"(v)); return r; }

__device__ __forceinline__ int s_off(int kc, int g)
{ return OFF_S + kc * BQ + (((g + kc + (kc >> 3)) & 31) << 2); }

// 10*tanh(x) = 10 - 20/(exp(2x)+1); exact at +/-inf, no clamp needed
__device__ __forceinline__ float tanh10(float x)
{
    float e = __expf(2.f * x);
    float r;
    asm("rcp.approx.f32 %0,%1;" : "=f"(r) : "f"(e + 1.f));
    return fmaf(-20.f, r, 10.f);
}

__device__ float g_q[BATCH * LQ * QKV_N];
__device__ float g_k[BATCH * LK * QKV_N];
__device__ float g_v[BATCH * LK * QKV_N];
__device__ float g_otmp[BATCH * LQ * QKV_N];
__device__ float g_vsum[BATCH * QKV_N];
__device__ int g_mask_mode;  // 0=u8, 1=i32, 2=f32

__global__ void detect_mask_kernel(const unsigned int* __restrict__ w)
{
    __shared__ int s_f32, s_all01;
    if (threadIdx.x == 0) { s_f32 = 0; s_all01 = 1; }
    __syncthreads();
    int f = 0, bad = 0;
    for (int i = threadIdx.x; i < 2048; i += blockDim.x) {
        unsigned v = w[i];
        if (v == 0x3F800000u) f = 1;
        if (v > 1u) bad = 1;
    }
    if (f) atomicOr(&s_f32, 1);
    if (bad) atomicExch(&s_all01, 0);
    __syncthreads();
    if (threadIdx.x == 0) g_mask_mode = s_f32 ? 2 : (s_all01 ? 1 : 0);
}

// ---- fused QKV projection
__global__ __launch_bounds__(256) void gemm_qkv_kernel(
    const float* __restrict__ X0, const float* __restrict__ X1, const float* __restrict__ X2,
    const float* __restrict__ W0, const float* __restrict__ W1, const float* __restrict__ W2,
    const float* __restrict__ B0, const float* __restrict__ B1, const float* __restrict__ B2,
    float* __restrict__ Y0, float* __restrict__ Y1, float* __restrict__ Y2)
{
    __shared__ float xs[32 * 68];
    __shared__ float ws[32 * 132];
    int sel = blockIdx.y;
    const float* X = sel == 0 ? X0 : (sel == 1 ? X1 : X2);
    const float* W = sel == 0 ? W0 : (sel == 1 ? W1 : W2);
    const float* bias = sel == 0 ? B0 : (sel == 1 ? B1 : B2);
    float* Y = sel == 0 ? Y0 : (sel == 1 ? Y1 : Y2);

    int tid = threadIdx.x;
    int tx = tid & 15, ty = tid >> 4;
    int bm = blockIdx.x * 64;
    int row0 = ty * 4, col0 = tx * 8;

    ull acc2[4][4];
#pragma unroll
    for (int i = 0; i < 4; i++)
#pragma unroll
        for (int j = 0; j < 4; j++) acc2[i][j] = 0ull;

    for (int k0 = 0; k0 < DMODEL; k0 += 32) {
#pragma unroll
        for (int i = 0; i < 2; i++) {
            int linear = tid + i * 256;
            int m = linear >> 3;
            int g = (linear & 7) * 4;
            float4 v = *(const float4*)&X[(size_t)(bm + m) * DMODEL + k0 + g];
            xs[(g + 0) * 68 + m] = v.x;
            xs[(g + 1) * 68 + m] = v.y;
            xs[(g + 2) * 68 + m] = v.z;
            xs[(g + 3) * 68 + m] = v.w;
        }
#pragma unroll
        for (int i = 0; i < 4; i++) {
            int linear = tid + i * 256;
            int k = linear >> 5;
            int g = (linear & 31) * 4;
            *(float4*)&ws[k * 132 + g] = *(const float4*)&W[(size_t)(k0 + k) * QKV_N + g];
        }
        __syncthreads();
#pragma unroll
        for (int k = 0; k < 32; k++) {
            float4 xa = *(const float4*)&xs[k * 68 + row0];
            float4 wa = *(const float4*)&ws[k * 132 + col0];
            float4 wb = *(const float4*)&ws[k * 132 + col0 + 4];
            ull wp[4] = {pk2(wa.x, wa.y), pk2(wa.z, wa.w),
                         pk2(wb.x, wb.y), pk2(wb.z, wb.w)};
            ull xb[4] = {bc2(xa.x), bc2(xa.y), bc2(xa.z), bc2(xa.w)};
#pragma unroll
            for (int i = 0; i < 4; i++)
#pragma unroll
                for (int j = 0; j < 4; j++)
                    fma2(acc2[i][j], xb[i], wp[j]);
        }
        __syncthreads();
    }
    float bb[8];
#pragma unroll
    for (int j = 0; j < 8; j++) bb[j] = bias[col0 + j];
#pragma unroll
    for (int i = 0; i < 4; i++) {
        float2 a0 = up2(acc2[i][0]), a1 = up2(acc2[i][1]);
        float2 a2 = up2(acc2[i][2]), a3 = up2(acc2[i][3]);
        float* yp = &Y[(size_t)(bm + row0 + i) * QKV_N + col0];
        *(float4*)yp = make_float4(a0.x + bb[0], a0.y + bb[1], a1.x + bb[2], a1.y + bb[3]);
        *(float4*)(yp + 4) = make_float4(a2.x + bb[4], a2.y + bb[5], a3.x + bb[6], a3.y + bb[7]);
    }
}

// ---- out-proj GEMM
__global__ __launch_bounds__(256) void gemm_bias_kernel(
    const float* __restrict__ X, const float* __restrict__ W,
    const float* __restrict__ bias, float* __restrict__ Y,
    int M, int K, int N)
{
    __shared__ float xs[32 * 68];
    __shared__ float ws[32 * 132];
    int tid = threadIdx.x;
    int tx = tid & 15, ty = tid >> 4;
    int bm = blockIdx.x * 64, bn = blockIdx.y * 128;
    int row0 = ty * 4, col0 = tx * 8;

    ull acc2[4][4];
#pragma unroll
    for (int i = 0; i < 4; i++)
#pragma unroll
        for (int j = 0; j < 4; j++) acc2[i][j] = 0ull;

    for (int k0 = 0; k0 < K; k0 += 32) {
#pragma unroll
        for (int i = 0; i < 2; i++) {
            int linear = tid + i * 256;
            int m = linear >> 3;
            int g = (linear & 7) * 4;
            float4 v = *(const float4*)&X[(size_t)(bm + m) * K + k0 + g];
            xs[(g + 0) * 68 + m] = v.x;
            xs[(g + 1) * 68 + m] = v.y;
            xs[(g + 2) * 68 + m] = v.z;
            xs[(g + 3) * 68 + m] = v.w;
        }
#pragma unroll
        for (int i = 0; i < 4; i++) {
            int linear = tid + i * 256;
            int k = linear >> 5;
            int g = (linear & 31) * 4;
            *(float4*)&ws[k * 132 + g] = *(const float4*)&W[(size_t)(k0 + k) * N + bn + g];
        }
        __syncthreads();
#pragma unroll
        for (int k = 0; k < 32; k++) {
            float4 xa = *(const float4*)&xs[k * 68 + row0];
            float4 wa = *(const float4*)&ws[k * 132 + col0];
            float4 wb = *(const float4*)&ws[k * 132 + col0 + 4];
            ull wp[4] = {pk2(wa.x, wa.y), pk2(wa.z, wa.w),
                         pk2(wb.x, wb.y), pk2(wb.z, wb.w)};
            ull xb[4] = {bc2(xa.x), bc2(xa.y), bc2(xa.z), bc2(xa.w)};
#pragma unroll
            for (int i = 0; i < 4; i++)
#pragma unroll
                for (int j = 0; j < 4; j++)
                    fma2(acc2[i][j], xb[i], wp[j]);
        }
        __syncthreads();
    }
    float bb[8];
#pragma unroll
    for (int j = 0; j < 8; j++) bb[j] = bias[bn + col0 + j];
#pragma unroll
    for (int i = 0; i < 4; i++) {
        float2 a0 = up2(acc2[i][0]), a1 = up2(acc2[i][1]);
        float2 a2 = up2(acc2[i][2]), a3 = up2(acc2[i][3]);
        float* yp = &Y[(size_t)(bm + row0 + i) * N + bn + col0];
        *(float4*)yp = make_float4(a0.x + bb[0], a0.y + bb[1], a1.x + bb[2], a1.y + bb[3]);
        *(float4*)(yp + 4) = make_float4(a2.x + bb[4], a2.y + bb[5], a3.x + bb[6], a3.y + bb[7]);
    }
}

__global__ void vsum_zero_kernel() { g_vsum[threadIdx.x] = 0.f; }

__global__ __launch_bounds__(256) void vsum_kernel()
{
    __shared__ float red[8][128];
    int b = blockIdx.x, part = blockIdx.y;
    int c4 = (threadIdx.x & 31) * 4;
    int r0 = threadIdx.x >> 5;
    const float* base = g_v + ((size_t)b * LK + part * 128) * QKV_N;
    float4 s = make_float4(0.f, 0.f, 0.f, 0.f);
#pragma unroll 4
    for (int r = r0; r < 128; r += 8) {
        float4 v = *(const float4*)&base[(size_t)r * QKV_N + c4];
        s.x += v.x; s.y += v.y; s.z += v.z; s.w += v.w;
    }
    *(float4*)&red[r0][c4] = s;
    __syncthreads();
    if (threadIdx.x < 128) {
        float t = 0.f;
#pragma unroll
        for (int i = 0; i < 8; i++) t += red[i][threadIdx.x];
        atomicAdd(&g_vsum[b * QKV_N + threadIdx.x], t);
    }
}

// one block = 128 queries for one (b,h); 256 threads; 8x8 QK frag, 8x4 SV frag
__global__ __launch_bounds__(256) void mab_main_kernel(
    const void* __restrict__ maskp, float* __restrict__ attn)
{
    extern __shared__ float sm[];
    int tid = threadIdx.x;
    int tx = tid & 15, ty = tid >> 4;
    int m0 = ty * 8;
    int nk = tx * 8;
    int nv = tx * 4;
    int q0 = blockIdx.x * BQ;
    int h = blockIdx.y, b = blockIdx.z;
    int mode = g_mask_mode;

    const float* qbase = g_q + ((size_t)b * LQ + q0) * QKV_N + h * DK;
#pragma unroll
    for (int i = 0; i < 8; i++) {
        int linear = tid + i * 256;
        int m = linear >> 4;
        int d = (linear & 15) * 4;
        float4 v = *(const float4*)&qbase[(size_t)m * QKV_N + d];
        sm[OFF_Q + (d + 0) * Q_STR + m] = v.x * 0.125f;
        sm[OFF_Q + (d + 1) * Q_STR + m] = v.y * 0.125f;
        sm[OFF_Q + (d + 2) * Q_STR + m] = v.z * 0.125f;
        sm[OFF_Q + (d + 3) * Q_STR + m] = v.w * 0.125f;
    }
    if (tid < BQ) sm[OFF_RL + tid] = 0.f;

    ull sv2[4][4];
#pragma unroll
    for (int i = 0; i < 4; i++)
#pragma unroll
        for (int j = 0; j < 4; j++) sv2[i][j] = 0ull;

    const float* kbase = g_k + (size_t)b * LK * QKV_N + h * DK;
    const float* vbase = g_v + (size_t)b * LK * QKV_N + h * DK;
    float* arow = attn + ((size_t)((b * NH + h) * LQ + q0)) * LK;

    __syncthreads();

    for (int c = 0; c < LK / BK; c++) {
        int k0 = c * BK;
#pragma unroll
        for (int i = 0; i < 8; i++) {
            int linear = tid + i * 256;
            int kr = linear >> 4;
            int d = (linear & 15) * 4;
            float4 v = *(const float4*)&kbase[(size_t)(k0 + kr) * QKV_N + d];
            sm[OFF_K + (d + 0) * K_STR + kr] = v.x;
            sm[OFF_K + (d + 1) * K_STR + kr] = v.y;
            sm[OFF_K + (d + 2) * K_STR + kr] = v.z;
            sm[OFF_K + (d + 3) * K_STR + kr] = v.w;
        }
#pragma unroll
        for (int i = 0; i < 8; i++) {
            int linear = tid + i * 256;
            int kr = linear >> 4;
            int d = (linear & 15) * 4;
            *(float4*)&sm[OFF_V + kr * DV + d] =
                *(const float4*)&vbase[(size_t)(k0 + kr) * QKV_N + d];
        }
        if (tid < BK) {
            size_t gi = (size_t)b * LK + k0 + tid;
            int mm;
            if (mode == 1)      mm = ((const int*)maskp)[gi] != 0;
            else if (mode == 0) mm = ((const unsigned char*)maskp)[gi] != 0;
            else                mm = ((const float*)maskp)[gi] != 0.f;
            sm[OFF_MSK + tid] = mm ? 1.f : 0.f;
        }
        __syncthreads();

        // phase 1: S = q @ k^T, 8 queries x 8 keys per thread
        ull acc2[4][8];
#pragma unroll
        for (int p = 0; p < 4; p++)
#pragma unroll
            for (int j = 0; j < 8; j++) acc2[p][j] = 0ull;

#pragma unroll 4
        for (int d = 0; d < DK; d++) {
            float4 qa = *(const float4*)&sm[OFF_Q + d * Q_STR + m0];
            float4 qb = *(const float4*)&sm[OFF_Q + d * Q_STR + m0 + 4];
            float4 ka = *(const float4*)&sm[OFF_K + d * K_STR + nk];
            float4 kb4 = *(const float4*)&sm[OFF_K + d * K_STR + nk + 4];
            ull qp[4] = {pk2(qa.x, qa.y), pk2(qa.z, qa.w),
                         pk2(qb.x, qb.y), pk2(qb.z, qb.w)};
            ull kb[8] = {bc2(ka.x), bc2(ka.y), bc2(ka.z), bc2(ka.w),
                         bc2(kb4.x), bc2(kb4.y), bc2(kb4.z), bc2(kb4.w)};
#pragma unroll
            for (int p = 0; p < 4; p++)
#pragma unroll
                for (int j = 0; j < 8; j++)
                    fma2(acc2[p][j], qp[p], kb[j]);
        }

        float acc[8][8];
#pragma unroll
        for (int p = 0; p < 4; p++)
#pragma unroll
            for (int j = 0; j < 8; j++) {
                float2 v = up2(acc2[p][j]);
                acc[2 * p][j] = v.x;
                acc[2 * p + 1][j] = v.y;
            }

        float mk[8];
#pragma unroll
        for (int j = 0; j < 8; j++) mk[j] = sm[OFF_MSK + nk + j];

        // tanh-clip + mask + gmem write + fused exp row-sums
        float er[8];
#pragma unroll
        for (int i = 0; i < 8; i++) {
            float rs = 0.f;
#pragma unroll
            for (int j = 0; j < 8; j++) {
                float s = tanh10(acc[i][j]);
                if (mk[j] != 0.f) s = -10.f;
                acc[i][j] = s;
                rs += __expf(s);
            }
            er[i] = rs;
            float* ap = &arow[(size_t)(m0 + i) * LK + k0 + nk];
            *(float4*)ap = make_float4(acc[i][0], acc[i][1], acc[i][2], acc[i][3]);
            *(float4*)(ap + 4) = make_float4(acc[i][4], acc[i][5], acc[i][6], acc[i][7]);
        }
        // butterfly over the 16 tx lanes (lane = (ty&1)*16 + tx; xor<16 stays in half)
#pragma unroll
        for (int d = 1; d < 16; d <<= 1) {
#pragma unroll
            for (int i = 0; i < 8; i++)
                er[i] += __shfl_xor_sync(0xffffffffu, er[i], d);
        }
        if (tx == 0) {
#pragma unroll
            for (int i = 0; i < 8; i++)
                sm[OFF_RL + m0 + i] += er[i];
        }
        {
            int g = m0 >> 2;
#pragma unroll
            for (int j = 0; j < 8; j++) {
                int kc = nk + j;
                *(float4*)&sm[s_off(kc, g)] =
                    make_float4(acc[0][j], acc[1][j], acc[2][j], acc[3][j]);
                *(float4*)&sm[s_off(kc, g + 1)] =
                    make_float4(acc[4][j], acc[5][j], acc[6][j], acc[7][j]);
            }
        }
        __syncthreads();

        // phase 2: SV += S_chunk @ v_chunk (8 queries x 4 dv per thread)
        {
            int g = m0 >> 2;
#pragma unroll 8
            for (int kc = 0; kc < BK; kc++) {
                float4 sa = *(const float4*)&sm[s_off(kc, g)];
                float4 sb = *(const float4*)&sm[s_off(kc, g + 1)];
                float4 vv = *(const float4*)&sm[OFF_V + kc * DV + nv];
                ull sp[4] = {pk2(sa.x, sa.y), pk2(sa.z, sa.w),
                             pk2(sb.x, sb.y), pk2(sb.z, sb.w)};
                ull vb[4] = {bc2(vv.x), bc2(vv.y), bc2(vv.z), bc2(vv.w)};
#pragma unroll
                for (int p = 0; p < 4; p++)
#pragma unroll
                    for (int j = 0; j < 4; j++)
                        fma2(sv2[p][j], sp[p], vb[j]);
            }
        }
        __syncthreads();
    }

    if (tid < BQ) sm[OFF_LSE + tid] = logf(sm[OFF_RL + tid]);
    __syncthreads();

    {   // otmp = SV - lse * vsum
        float4 vs = *(const float4*)&g_vsum[(b * NH + h) * DV + nv];
#pragma unroll
        for (int p = 0; p < 4; p++) {
            float2 c0 = up2(sv2[p][0]), c1 = up2(sv2[p][1]);
            float2 c2 = up2(sv2[p][2]), c3 = up2(sv2[p][3]);
            float l0 = sm[OFF_LSE + m0 + 2 * p];
            float l1 = sm[OFF_LSE + m0 + 2 * p + 1];
            size_t r0 = ((size_t)b * LQ + q0 + m0 + 2 * p) * QKV_N + h * DK + nv;
            *(float4*)&g_otmp[r0] =
                make_float4(c0.x - l0 * vs.x, c1.x - l0 * vs.y,
                            c2.x - l0 * vs.z, c3.x - l0 * vs.w);
            *(float4*)&g_otmp[r0 + QKV_N] =
                make_float4(c0.y - l1 * vs.x, c1.y - l1 * vs.y,
                            c2.y - l1 * vs.z, c3.y - l1 * vs.w);
        }
    }

    float lr[8];
#pragma unroll
    for (int i = 0; i < 8; i++) lr[i] = sm[OFF_LSE + m0 + i];
    for (int c = 0; c < LK / BK; c++) {
#pragma unroll
        for (int i = 0; i < 8; i++) {
            float* ap = &arow[(size_t)(m0 + i) * LK + c * BK + nk];
            float4 a = *(float4*)ap;
            a.x -= lr[i]; a.y -= lr[i]; a.z -= lr[i]; a.w -= lr[i];
            *(float4*)ap = a;
            float4 b4 = *(float4*)(ap + 4);
            b4.x -= lr[i]; b4.y -= lr[i]; b4.z -= lr[i]; b4.w -= lr[i];
            *(float4*)(ap + 4) = b4;
        }
    }
}

extern "C" void kernel_launch(void* const* d_in, const int* in_sizes, int n_in,
                              void* d_out, int out_size)
{
    const float* Q  = (const float*)d_in[0];
    const float* K  = (const float*)d_in[1];
    const float* V  = (const float*)d_in[2];
    const void*  Mk = d_in[3];
    const float* Wq = (const float*)d_in[4];
    const float* bq = (const float*)d_in[5];
    const float* Wk = (const float*)d_in[6];
    const float* bk = (const float*)d_in[7];
    const float* Wv = (const float*)d_in[8];
    const float* bv = (const float*)d_in[9];
    const float* Wo = (const float*)d_in[10];
    const float* bo = (const float*)d_in[11];

    float* out  = (float*)d_out;
    float* attn = out + (size_t)BATCH * LQ * DMODEL;

    float *gq, *gk, *gv, *gotmp;
    cudaGetSymbolAddress((void**)&gq, g_q);
    cudaGetSymbolAddress((void**)&gk, g_k);
    cudaGetSymbolAddress((void**)&gv, g_v);
    cudaGetSymbolAddress((void**)&gotmp, g_otmp);

    static int smem_set = 0;
    if (!smem_set) {
        cudaFuncSetAttribute(mab_main_kernel,
                             cudaFuncAttributeMaxDynamicSharedMemorySize, SMEM_BYTES);
        smem_set = 1;
    }

    detect_mask_kernel<<<1, 256>>>((const unsigned int*)Mk);

    const int M = BATCH * LQ;  // 8192
    gemm_qkv_kernel<<<dim3(M / 64, 3), 256>>>(Q, K, V, Wq, Wk, Wv,
                                              bq, bk, bv, gq, gk, gv);

    vsum_zero_kernel<<<1, BATCH * QKV_N>>>();
    vsum_kernel<<<dim3(BATCH, 16), 256>>>();

    mab_main_kernel<<<dim3(LQ / BQ, NH, BATCH), 256, SMEM_BYTES>>>(Mk, attn);

    gemm_bias_kernel<<<dim3(M / 64, DMODEL / 128), 256>>>(gotmp, Wo, bo, out,
                                                          M, QKV_N, DMODEL);
}